// round 2
// baseline (speedup 1.0000x reference)
#include <cuda_runtime.h>
#include <math.h>

// Problem constants
#define BB 32
#define NT 577
#define HH 12
#define DD 64
#define CC 768
#define MM (BB * NT)        // 18464 rows
#define QKV_N (3 * CC)      // 2304

// Scratch (static device arrays: allocation-free per harness rules)
__device__ float g_q[(size_t)BB * HH * NT * DD];   // [B,H,N,D], pre-scaled by D^-0.5
__device__ float g_k[(size_t)BB * HH * NT * DD];   // [B,H,N,D]
__device__ float g_v[(size_t)BB * HH * NT * DD];   // [B,H,N,D]
__device__ float g_o[(size_t)BB * NT * HH * DD];   // [B,N,H,D] == [M, 768]

// Fast exp on the FMA pipe (avoids MUFU throughput wall: 128M exps needed).
// exp(x) = 2^(x*log2e); n = rint(y), f in [-0.5,0.5], degree-6 Taylor for 2^f.
// Relative error ~1e-7. Input clamped to >= -80 (=> exponent >= -116, no underflow UB).
__device__ __forceinline__ float fexp(float x) {
    x = fmaxf(x, -80.0f);
    float y = x * 1.4426950408889634f;
    float n = rintf(y);
    float f = y - n;
    float p = 1.5402356e-4f;
    p = fmaf(p, f, 1.3333558e-3f);
    p = fmaf(p, f, 9.6181291e-3f);
    p = fmaf(p, f, 5.5504109e-2f);
    p = fmaf(p, f, 2.4022651e-1f);
    p = fmaf(p, f, 6.9314718e-1f);
    p = fmaf(p, f, 1.0f);
    return p * __int_as_float(((int)n + 127) << 23);
}

// ---------------------------------------------------------------------------
// SGEMM: C[M, Ncols] = A[M,K] * W[Ncols,K]^T (+ epilogue)
// 128x128 tile, BK=8, 256 threads, 8x8 per-thread microtile.
// MODE 0: A = x, W = qkv_w. Epilogue: +bias, RoPE on q/k, scale q, scatter to
//         g_q/g_k/g_v in [B,H,N,D].
// MODE 1: A = g_o, W = proj_w. Epilogue: +proj_b, write to out [M,768].
// ---------------------------------------------------------------------------
#define SMPAD 132   // 128 + 4 pad: kills bank conflicts on transposed stores

template <int MODE>
__global__ __launch_bounds__(256)
void gemm_kernel(const float* __restrict__ A, const float* __restrict__ W,
                 const float* __restrict__ b0, const float* __restrict__ b1,
                 const float* __restrict__ rope, float* __restrict__ Cout,
                 int K)
{
    __shared__ float As[8][SMPAD];
    __shared__ float Ws[8][SMPAD];

    const int tid = threadIdx.x;
    const int tx = tid & 15;
    const int ty = tid >> 4;
    const int rowBase = blockIdx.y * 128;
    const int colBase = blockIdx.x * 128;

    const float* Aeff = (MODE == 1) ? g_o : A;

    float acc[8][8];
#pragma unroll
    for (int i = 0; i < 8; ++i)
#pragma unroll
        for (int j = 0; j < 8; ++j) acc[i][j] = 0.0f;

    const int lr = tid >> 1;            // 0..127
    const int lk = (tid & 1) << 2;      // 0 or 4
    const float* Ap = Aeff + (size_t)(rowBase + lr) * K + lk;
    const float* Wp = W + (size_t)(colBase + lr) * K + lk;
    const bool a_valid = (rowBase + lr) < MM;

    for (int k0 = 0; k0 < K; k0 += 8) {
        float4 a4 = a_valid ? *(const float4*)(Ap + k0) : make_float4(0.f, 0.f, 0.f, 0.f);
        float4 w4 = *(const float4*)(Wp + k0);
        __syncthreads();
        As[lk + 0][lr] = a4.x; As[lk + 1][lr] = a4.y;
        As[lk + 2][lr] = a4.z; As[lk + 3][lr] = a4.w;
        Ws[lk + 0][lr] = w4.x; Ws[lk + 1][lr] = w4.y;
        Ws[lk + 2][lr] = w4.z; Ws[lk + 3][lr] = w4.w;
        __syncthreads();
#pragma unroll
        for (int kk = 0; kk < 8; ++kk) {
            float4 x0 = *(const float4*)&As[kk][ty * 8];
            float4 x1 = *(const float4*)&As[kk][ty * 8 + 4];
            float4 y0 = *(const float4*)&Ws[kk][tx * 8];
            float4 y1 = *(const float4*)&Ws[kk][tx * 8 + 4];
            float ra[8] = {x0.x, x0.y, x0.z, x0.w, x1.x, x1.y, x1.z, x1.w};
            float rw[8] = {y0.x, y0.y, y0.z, y0.w, y1.x, y1.y, y1.z, y1.w};
#pragma unroll
            for (int i = 0; i < 8; ++i)
#pragma unroll
                for (int j = 0; j < 8; ++j)
                    acc[i][j] = fmaf(ra[i], rw[j], acc[i][j]);
        }
    }

    const int col0 = colBase + tx * 8;   // 8-aligned => whole RoPE pairs, single head

    if (MODE == 0) {
        const int which = col0 / CC;             // 0=q, 1=k, 2=v
        const int r0 = col0 - which * CC;        // channel within [0,768)
        const int h = r0 >> 6;
        const int d0 = r0 & 63;
        float bias[8];
#pragma unroll
        for (int j = 0; j < 8; ++j)
            bias[j] = (which == 0) ? b0[r0 + j] : ((which == 2) ? b1[r0 + j] : 0.0f);
        float* dst = (which == 0) ? g_q : ((which == 1) ? g_k : g_v);

#pragma unroll
        for (int i = 0; i < 8; ++i) {
            int m = rowBase + ty * 8 + i;
            if (m >= MM) break;
            int bb = m / NT;
            int t = m - bb * NT;
            float vals[8];
#pragma unroll
            for (int j = 0; j < 8; ++j) vals[j] = acc[i][j] + bias[j];

            if (which < 2 && t > 0) {
                const float* rp = rope + (size_t)(t - 1) * (2 * DD);
                float4 s0 = *(const float4*)(rp + d0);
                float4 s1 = *(const float4*)(rp + d0 + 4);
                float4 c0 = *(const float4*)(rp + DD + d0);
                float4 c1 = *(const float4*)(rp + DD + d0 + 4);
                float sn[8] = {s0.x, s0.y, s0.z, s0.w, s1.x, s1.y, s1.z, s1.w};
                float cs[8] = {c0.x, c0.y, c0.z, c0.w, c1.x, c1.y, c1.z, c1.w};
#pragma unroll
                for (int p = 0; p < 4; ++p) {
                    float xe = vals[2 * p], xo = vals[2 * p + 1];
                    vals[2 * p]     = xe * cs[2 * p]     - xo * sn[2 * p];
                    vals[2 * p + 1] = xo * cs[2 * p + 1] + xe * sn[2 * p + 1];
                }
            }
            if (which == 0) {
#pragma unroll
                for (int j = 0; j < 8; ++j) vals[j] *= 0.125f;  // D^-0.5
            }
            float* op = dst + ((((size_t)bb * HH + h) * NT + t) * DD + d0);
            *(float4*)op       = make_float4(vals[0], vals[1], vals[2], vals[3]);
            *(float4*)(op + 4) = make_float4(vals[4], vals[5], vals[6], vals[7]);
        }
    } else {
        float bias[8];
#pragma unroll
        for (int j = 0; j < 8; ++j) bias[j] = b0[col0 + j];
#pragma unroll
        for (int i = 0; i < 8; ++i) {
            int m = rowBase + ty * 8 + i;
            if (m >= MM) break;
            float* op = Cout + (size_t)m * CC + col0;
            *(float4*)op = make_float4(acc[i][0] + bias[0], acc[i][1] + bias[1],
                                       acc[i][2] + bias[2], acc[i][3] + bias[3]);
            *(float4*)(op + 4) = make_float4(acc[i][4] + bias[4], acc[i][5] + bias[5],
                                             acc[i][6] + bias[6], acc[i][7] + bias[7]);
        }
    }
}

// ---------------------------------------------------------------------------
// Flash attention, fp32, online softmax.
// Grid: (10 q-tiles, B*H). 256 threads, 4x4 microtile over a 64x64 S tile.
// Smem: Qs[d][i], Ks[d][j] (transposed), Vs[j][d], Ps[i][j] (pad 68), stats.
// ---------------------------------------------------------------------------
#define PST 68
#define FLASH_SMEM ((3 * 64 * 64 + 64 * PST + 3 * 64) * 4)

__global__ __launch_bounds__(256)
void flash_kernel()
{
    extern __shared__ float sm[];
    float* Qs = sm;                       // [64][64] (d-major)
    float* Ks = sm + 4096;                // [64][64] (d-major)
    float* Vs = sm + 8192;                // [64][64] (j-major)
    float* Ps = sm + 12288;               // [64][PST]
    float* m_s = sm + 12288 + 64 * PST;   // [64]
    float* l_s = m_s + 64;                // [64]
    float* sc_s = l_s + 64;               // [64]

    const int tid = threadIdx.x;
    const int tx = tid & 15;
    const int ty = tid >> 4;
    const int bh = blockIdx.y;
    const int b = bh / HH;
    const int h = bh - b * HH;
    const int qbase = blockIdx.x * 64;
    const size_t head_off = ((size_t)b * HH + h) * NT * DD;

    // Load Q tile transposed; zero-pad invalid query rows.
    {
        int r = tid >> 2;
        int dc = (tid & 3) << 4;
        const float* src = g_q + head_off + (size_t)(qbase + r) * DD;
        bool valid = (qbase + r) < NT;
#pragma unroll
        for (int u = 0; u < 4; ++u) {
            float4 v = valid ? *(const float4*)(src + dc + u * 4)
                             : make_float4(0.f, 0.f, 0.f, 0.f);
            int d = dc + u * 4;
            Qs[(d + 0) * 64 + r] = v.x; Qs[(d + 1) * 64 + r] = v.y;
            Qs[(d + 2) * 64 + r] = v.z; Qs[(d + 3) * 64 + r] = v.w;
        }
    }
    if (tid < 64) { m_s[tid] = -1e30f; l_s[tid] = 0.0f; }

    float oa[4][4];
#pragma unroll
    for (int i = 0; i < 4; ++i)
#pragma unroll
        for (int c = 0; c < 4; ++c) oa[i][c] = 0.0f;

    for (int t = 0; t < 10; ++t) {
        const int kvbase = t * 64;
        const int vrows = (NT - kvbase < 64) ? (NT - kvbase) : 64;
        __syncthreads();  // previous O-phase done with Vs/Ps; safe to overwrite
        {
            int r = tid >> 2;
            int dc = (tid & 3) << 4;
            const float* ksrc = g_k + head_off + (size_t)(kvbase + r) * DD;
            const float* vsrc = g_v + head_off + (size_t)(kvbase + r) * DD;
            bool valid = r < vrows;
#pragma unroll
            for (int u = 0; u < 4; ++u) {
                int d = dc + u * 4;
                float4 kv = valid ? *(const float4*)(ksrc + d)
                                  : make_float4(0.f, 0.f, 0.f, 0.f);
                Ks[(d + 0) * 64 + r] = kv.x; Ks[(d + 1) * 64 + r] = kv.y;
                Ks[(d + 2) * 64 + r] = kv.z; Ks[(d + 3) * 64 + r] = kv.w;
                float4 vv = valid ? *(const float4*)(vsrc + d)
                                  : make_float4(0.f, 0.f, 0.f, 0.f);
                *(float4*)&Vs[r * 64 + d] = vv;
            }
        }
        __syncthreads();

        // S = Q K^T (per-thread 4x4)
        float s[4][4];
#pragma unroll
        for (int i = 0; i < 4; ++i)
#pragma unroll
            for (int j = 0; j < 4; ++j) s[i][j] = 0.0f;
#pragma unroll 8
        for (int d = 0; d < 64; ++d) {
            float4 qv = *(const float4*)&Qs[d * 64 + ty * 4];
            float4 kv = *(const float4*)&Ks[d * 64 + tx * 4];
            float rq[4] = {qv.x, qv.y, qv.z, qv.w};
            float rk[4] = {kv.x, kv.y, kv.z, kv.w};
#pragma unroll
            for (int i = 0; i < 4; ++i)
#pragma unroll
                for (int j = 0; j < 4; ++j)
                    s[i][j] = fmaf(rq[i], rk[j], s[i][j]);
        }
        // mask invalid key columns
#pragma unroll
        for (int j = 0; j < 4; ++j) {
            if (kvbase + tx * 4 + j >= NT) {
#pragma unroll
                for (int i = 0; i < 4; ++i) s[i][j] = -1e30f;
            }
        }
        // row max across the 16-lane tx-group (same warp half)
        float rmax[4];
#pragma unroll
        for (int i = 0; i < 4; ++i)
            rmax[i] = fmaxf(fmaxf(s[i][0], s[i][1]), fmaxf(s[i][2], s[i][3]));
#pragma unroll
        for (int off = 8; off > 0; off >>= 1)
#pragma unroll
            for (int i = 0; i < 4; ++i)
                rmax[i] = fmaxf(rmax[i], __shfl_xor_sync(0xffffffffu, rmax[i], off));

        float mold[4], mnew[4], rsum[4];
#pragma unroll
        for (int i = 0; i < 4; ++i) {
            mold[i] = m_s[ty * 4 + i];
            mnew[i] = fmaxf(mold[i], rmax[i]);
        }
        float p[4][4];
#pragma unroll
        for (int i = 0; i < 4; ++i) {
            rsum[i] = 0.0f;
#pragma unroll
            for (int j = 0; j < 4; ++j) {
                p[i][j] = fexp(s[i][j] - mnew[i]);
                rsum[i] += p[i][j];
            }
        }
#pragma unroll
        for (int off = 8; off > 0; off >>= 1)
#pragma unroll
            for (int i = 0; i < 4; ++i)
                rsum[i] += __shfl_xor_sync(0xffffffffu, rsum[i], off);

#pragma unroll
        for (int i = 0; i < 4; ++i)
            *(float4*)&Ps[(ty * 4 + i) * PST + tx * 4] =
                make_float4(p[i][0], p[i][1], p[i][2], p[i][3]);

        if (tx == 0) {
#pragma unroll
            for (int i = 0; i < 4; ++i) {
                int r = ty * 4 + i;
                float scl = fexp(mold[i] - mnew[i]);
                m_s[r] = mnew[i];
                sc_s[r] = scl;
                l_s[r] = l_s[r] * scl + rsum[i];
            }
        }
        __syncthreads();

        // O = diag(scale) * O + P V
#pragma unroll
        for (int i = 0; i < 4; ++i) {
            float scl = sc_s[ty * 4 + i];
#pragma unroll
            for (int c = 0; c < 4; ++c) oa[i][c] *= scl;
        }
#pragma unroll 4
        for (int j = 0; j < 64; ++j) {
            float4 vv = *(const float4*)&Vs[j * 64 + tx * 4];
#pragma unroll
            for (int i = 0; i < 4; ++i) {
                float pv = Ps[(ty * 4 + i) * PST + j];
                oa[i][0] = fmaf(pv, vv.x, oa[i][0]);
                oa[i][1] = fmaf(pv, vv.y, oa[i][1]);
                oa[i][2] = fmaf(pv, vv.z, oa[i][2]);
                oa[i][3] = fmaf(pv, vv.w, oa[i][3]);
            }
        }
    }

    // normalize + write [B,N,H,D]
#pragma unroll
    for (int i = 0; i < 4; ++i) {
        int qr = qbase + ty * 4 + i;
        if (qr < NT) {
            float inv = 1.0f / l_s[ty * 4 + i];
            float* op = g_o + (((size_t)b * NT + qr) * HH + h) * DD + tx * 4;
            *(float4*)op = make_float4(oa[i][0] * inv, oa[i][1] * inv,
                                       oa[i][2] * inv, oa[i][3] * inv);
        }
    }
}

// ---------------------------------------------------------------------------

extern "C" void kernel_launch(void* const* d_in, const int* in_sizes, int n_in,
                              void* d_out, int out_size)
{
    const float* x      = (const float*)d_in[0];
    const float* rope   = (const float*)d_in[1];
    const float* qkv_w  = (const float*)d_in[2];
    const float* q_bias = (const float*)d_in[3];
    const float* v_bias = (const float*)d_in[4];
    const float* proj_w = (const float*)d_in[5];
    const float* proj_b = (const float*)d_in[6];
    float* out = (float*)d_out;

    (void)in_sizes; (void)n_in; (void)out_size;

    dim3 blk(256);
    const int mtiles = (MM + 127) / 128;  // 145

    // 1) QKV GEMM + bias + RoPE + q-scale, scatter to g_q/g_k/g_v
    gemm_kernel<0><<<dim3(QKV_N / 128, mtiles), blk>>>(
        x, qkv_w, q_bias, v_bias, rope, nullptr, CC);

    // 2) flash attention -> g_o
    cudaFuncSetAttribute(flash_kernel,
                         cudaFuncAttributeMaxDynamicSharedMemorySize, FLASH_SMEM);
    flash_kernel<<<dim3((NT + 63) / 64, BB * HH), blk, FLASH_SMEM>>>();

    // 3) output projection
    gemm_kernel<1><<<dim3(CC / 128, mtiles), blk>>>(
        nullptr, proj_w, proj_b, nullptr, nullptr, out, CC);
}

// round 5
// speedup vs baseline: 1.5298x; 1.5298x over previous
#include <cuda_runtime.h>
#include <cuda_bf16.h>
#include <cstdint>
#include <math.h>

// Problem constants
#define BB 32
#define NT 577
#define HH 12
#define DD 64
#define CC 768
#define MM (BB * NT)        // 18464
#define QKV_N (3 * CC)      // 2304

// ---------------------------------------------------------------------------
// Scratch (static device arrays: allocation-free per harness rules)
// ---------------------------------------------------------------------------
__device__ float g_q[(size_t)BB * HH * NT * DD];   // [B,H,N,D], pre-scaled
__device__ float g_k[(size_t)BB * HH * NT * DD];
__device__ float g_v[(size_t)BB * HH * NT * DD];

__device__ __nv_bfloat16 g_xhi[(size_t)MM * CC];
__device__ __nv_bfloat16 g_xlo[(size_t)MM * CC];
__device__ __nv_bfloat16 g_ohi[(size_t)MM * CC];   // attention out, [B,N,H*D]
__device__ __nv_bfloat16 g_olo[(size_t)MM * CC];
__device__ __nv_bfloat16 g_wqh[(size_t)QKV_N * CC];
__device__ __nv_bfloat16 g_wql[(size_t)QKV_N * CC];
__device__ __nv_bfloat16 g_wph[(size_t)CC * CC];
__device__ __nv_bfloat16 g_wpl[(size_t)CC * CC];

// ---------------------------------------------------------------------------
// Base-sm_100-safe PTX helpers (NO 'a'-gated instructions)
// ---------------------------------------------------------------------------
__device__ __forceinline__ uint32_t smem_u32(const void* p) {
    uint32_t a;
    asm("{ .reg .u64 t; cvta.to.shared.u64 t, %1; cvt.u32.u64 %0, t; }"
        : "=r"(a) : "l"(p));
    return a;
}

#define CP_ASYNC16(dst, src, sz) \
    asm volatile("cp.async.cg.shared.global [%0], [%1], 16, %2;" \
                 :: "r"(dst), "l"(src), "r"(sz))
#define CP_COMMIT() asm volatile("cp.async.commit_group;" ::: "memory")
#define CP_WAIT1()  asm volatile("cp.async.wait_group 1;" ::: "memory")
#define CP_WAIT0()  asm volatile("cp.async.wait_group 0;" ::: "memory")

__device__ __forceinline__ void ldsm_x4(uint32_t (&r)[4], uint32_t addr) {
    asm volatile("ldmatrix.sync.aligned.m8n8.x4.shared.b16 {%0,%1,%2,%3}, [%4];"
                 : "=r"(r[0]), "=r"(r[1]), "=r"(r[2]), "=r"(r[3]) : "r"(addr));
}

__device__ __forceinline__ void mma_bf16(float (&d)[4], const uint32_t (&a)[4],
                                         uint32_t b0, uint32_t b1) {
    asm volatile(
        "mma.sync.aligned.m16n8k16.row.col.f32.bf16.bf16.f32 "
        "{%0,%1,%2,%3}, {%4,%5,%6,%7}, {%8,%9}, {%0,%1,%2,%3};"
        : "+f"(d[0]), "+f"(d[1]), "+f"(d[2]), "+f"(d[3])
        : "r"(a[0]), "r"(a[1]), "r"(a[2]), "r"(a[3]), "r"(b0), "r"(b1));
}

// ---------------------------------------------------------------------------
// fp32 -> bf16 hi/lo split (fp32-class accuracy with bf16 MMAs)
// ---------------------------------------------------------------------------
__global__ __launch_bounds__(256)
void split_kernel(const float* __restrict__ x, const float* __restrict__ wq,
                  const float* __restrict__ wp)
{
    const int n0 = MM * CC / 4, n1 = QKV_N * CC / 4, n2 = CC * CC / 4;
    int i = blockIdx.x * blockDim.x + threadIdx.x;
    if (i >= n0 + n1 + n2) return;
    const float* src; __nv_bfloat16 *hp, *lp; int j;
    if (i < n0)           { src = x;  hp = g_xhi; lp = g_xlo; j = i; }
    else if (i < n0 + n1) { src = wq; hp = g_wqh; lp = g_wql; j = i - n0; }
    else                  { src = wp; hp = g_wph; lp = g_wpl; j = i - n0 - n1; }
    float4 v = ((const float4*)src)[j];
    float a[4] = {v.x, v.y, v.z, v.w};
    __nv_bfloat16 h4[4], l4[4];
#pragma unroll
    for (int u = 0; u < 4; ++u) {
        h4[u] = __float2bfloat16(a[u]);
        l4[u] = __float2bfloat16(a[u] - __bfloat162float(h4[u]));
    }
    __nv_bfloat162 p0, p1;
    p0.x = h4[0]; p0.y = h4[1]; p1.x = h4[2]; p1.y = h4[3];
    ((__nv_bfloat162*)(hp + 4 * (size_t)j))[0] = p0;
    ((__nv_bfloat162*)(hp + 4 * (size_t)j))[1] = p1;
    p0.x = l4[0]; p0.y = l4[1]; p1.x = l4[2]; p1.y = l4[3];
    ((__nv_bfloat162*)(lp + 4 * (size_t)j))[0] = p0;
    ((__nv_bfloat162*)(lp + 4 * (size_t)j))[1] = p1;
}

// ---------------------------------------------------------------------------
// mma.sync GEMM: C[M, Ncols] = A[M,K] * W[Ncols,K]^T with 2-term bf16 split.
// CTA tile 128x128, 8 warps (2x4), warp tile 64x32, BK=32, cp.async double buf.
// 3 MMAs per fragment pair: ah*bh + ah*bl + al*bh.
// MODE 0: A=x(hi/lo), B=qkv_w(hi/lo); epilogue bias+RoPE+scale, scatter q/k/v.
// MODE 1: A=o(hi/lo),  B=proj_w(hi/lo); epilogue +proj_b -> out.
// ---------------------------------------------------------------------------
#define LDK 40                        // padded row stride in bf16 (80 B)
#define ABYTES (128 * LDK * 2)        // 10240 B per array
#define STAGE_BYTES (4 * ABYTES)      // Ah, Al, Bh, Bl
#define GEMM_DSMEM (2 * STAGE_BYTES)  // 81920 B
#define NKIT (CC / 32)                // 24 K-chunks

template <int MODE>
__global__ __launch_bounds__(256)
void mma_gemm(const float* __restrict__ b0v, const float* __restrict__ b1v,
              const float* __restrict__ rope, float* __restrict__ Cout)
{
    extern __shared__ char dyn[];
    const uint32_t smem_base = smem_u32(dyn);

    const int tid = threadIdx.x;
    const int lane = tid & 31;
    const int wid = tid >> 5;
    const int wm = wid & 1;            // 2 warp-rows of 64
    const int wn = wid >> 1;           // 4 warp-cols of 32
    const int rowBase = blockIdx.y * 128;
    const int colBase = blockIdx.x * 128;

    const __nv_bfloat16* Ah = (MODE == 0) ? g_xhi : g_ohi;
    const __nv_bfloat16* Al = (MODE == 0) ? g_xlo : g_olo;
    const __nv_bfloat16* Bh = (MODE == 0) ? g_wqh : g_wph;
    const __nv_bfloat16* Bl = (MODE == 0) ? g_wql : g_wpl;

    // ---- stage loader: 2048 x 16B cp.async per stage, 8 per thread ----
    auto load_stage = [&](int stage, int k0) {
        const uint32_t sb = smem_base + stage * STAGE_BYTES;
#pragma unroll
        for (int t = 0; t < 8; ++t) {
            int c = t * 256 + tid;
            int arr = c >> 9;          // 0=Ah 1=Al 2=Bh 3=Bl
            int rid = c & 511;
            int row = rid >> 2;
            int kc = rid & 3;
            uint32_t dst = sb + arr * ABYTES + row * (LDK * 2) + kc * 16;
            const __nv_bfloat16* src;
            int sz = 16;
            if (arr < 2) {
                int m = rowBase + row;
                const __nv_bfloat16* p = arr ? Al : Ah;
                if (m < MM) src = p + (size_t)m * CC + k0 + kc * 8;
                else { src = p; sz = 0; }          // zero-fill pad rows
            } else {
                const __nv_bfloat16* p = (arr == 2) ? Bh : Bl;
                src = p + (size_t)(colBase + row) * CC + k0 + kc * 8;
            }
            CP_ASYNC16(dst, src, sz);
        }
    };

    float acc[4][4][4];
#pragma unroll
    for (int mf = 0; mf < 4; ++mf)
#pragma unroll
        for (int nf = 0; nf < 4; ++nf)
#pragma unroll
            for (int r = 0; r < 4; ++r) acc[mf][nf][r] = 0.0f;

    const uint32_t lrow = lane & 15;
    const uint32_t lhalf = (lane >> 4) * 8;

    load_stage(0, 0);
    CP_COMMIT();

    for (int c = 0; c < NKIT; ++c) {
        if (c + 1 < NKIT) {
            load_stage((c + 1) & 1, (c + 1) * 32);
            CP_COMMIT();
            CP_WAIT1();
        } else {
            CP_WAIT0();
        }
        __syncthreads();

        const uint32_t sb = smem_base + (c & 1) * STAGE_BYTES;
#pragma unroll
        for (int kk = 0; kk < 32; kk += 16) {
            uint32_t a_h[4][4], a_l[4][4];
#pragma unroll
            for (int mf = 0; mf < 4; ++mf) {
                uint32_t off = ((wm * 64 + mf * 16 + lrow) * LDK + kk + lhalf) * 2;
                ldsm_x4(a_h[mf], sb + off);
                ldsm_x4(a_l[mf], sb + ABYTES + off);
            }
            uint32_t bh[4][2], bl[4][2];
#pragma unroll
            for (int g = 0; g < 2; ++g) {
                uint32_t off = ((wn * 32 + g * 16 + lrow) * LDK + kk + lhalf) * 2;
                uint32_t r[4];
                ldsm_x4(r, sb + 2 * ABYTES + off);
                bh[g * 2][0] = r[0]; bh[g * 2][1] = r[2];
                bh[g * 2 + 1][0] = r[1]; bh[g * 2 + 1][1] = r[3];
                ldsm_x4(r, sb + 3 * ABYTES + off);
                bl[g * 2][0] = r[0]; bl[g * 2][1] = r[2];
                bl[g * 2 + 1][0] = r[1]; bl[g * 2 + 1][1] = r[3];
            }
#pragma unroll
            for (int mf = 0; mf < 4; ++mf)
#pragma unroll
                for (int nf = 0; nf < 4; ++nf) {
                    mma_bf16(acc[mf][nf], a_h[mf], bh[nf][0], bh[nf][1]);
                    mma_bf16(acc[mf][nf], a_h[mf], bl[nf][0], bl[nf][1]);
                    mma_bf16(acc[mf][nf], a_l[mf], bh[nf][0], bh[nf][1]);
                }
        }
        __syncthreads();
    }

    // ---- epilogue ----
    // c-frag: lane holds rows (r0, r0+8), col pair (c0, c0+1); c0 even => one
    // full RoPE rotation pair per float2 store.
    const int r0 = lane >> 2;
    const int c0 = (lane & 3) * 2;
    const int cb = colBase + wn * 32 + c0;

    if (MODE == 0) {
        const int which = colBase / CC;            // uniform per block
        float* dst0 = (which == 0) ? g_q : (which == 1) ? g_k : g_v;
#pragma unroll
        for (int mf = 0; mf < 4; ++mf) {
#pragma unroll
            for (int half = 0; half < 2; ++half) {
                int m = rowBase + wm * 64 + mf * 16 + r0 + half * 8;
                if (m >= MM) continue;
                int bbr = m / NT;
                int tt = m - bbr * NT;
                const float* rp = rope + (size_t)(tt - 1) * (2 * DD);
#pragma unroll
                for (int nf = 0; nf < 4; ++nf) {
                    int rel = cb + nf * 8 - which * CC;
                    int h = rel >> 6;
                    int d0i = rel & 63;
                    float v0 = acc[mf][nf][half * 2 + 0];
                    float v1 = acc[mf][nf][half * 2 + 1];
                    if (which == 0) { v0 += b0v[rel]; v1 += b0v[rel + 1]; }
                    else if (which == 2) { v0 += b1v[rel]; v1 += b1v[rel + 1]; }
                    if (which < 2 && tt > 0) {
                        float sn0 = rp[d0i], sn1 = rp[d0i + 1];
                        float cs0 = rp[DD + d0i], cs1 = rp[DD + d0i + 1];
                        float xe = v0, xo = v1;
                        v0 = xe * cs0 - xo * sn0;
                        v1 = xo * cs1 + xe * sn1;
                    }
                    if (which == 0) { v0 *= 0.125f; v1 *= 0.125f; }
                    float* dp = dst0 +
                        ((((size_t)bbr * HH + h) * NT + tt) * DD + d0i);
                    *(float2*)dp = make_float2(v0, v1);
                }
            }
        }
    } else {
#pragma unroll
        for (int mf = 0; mf < 4; ++mf) {
#pragma unroll
            for (int half = 0; half < 2; ++half) {
                int m = rowBase + wm * 64 + mf * 16 + r0 + half * 8;
                if (m >= MM) continue;
#pragma unroll
                for (int nf = 0; nf < 4; ++nf) {
                    int col = cb + nf * 8;
                    float v0 = acc[mf][nf][half * 2 + 0] + b0v[col];
                    float v1 = acc[mf][nf][half * 2 + 1] + b0v[col + 1];
                    *(float2*)(Cout + (size_t)m * CC + col) = make_float2(v0, v1);
                }
            }
        }
    }
}

// ---------------------------------------------------------------------------
// Fast exp on the FMA pipe (128M exps; MUFU would throttle)
// ---------------------------------------------------------------------------
__device__ __forceinline__ float fexp(float x) {
    x = fmaxf(x, -80.0f);
    float y = x * 1.4426950408889634f;
    float n = rintf(y);
    float f = y - n;
    float p = 1.5402356e-4f;
    p = fmaf(p, f, 1.3333558e-3f);
    p = fmaf(p, f, 9.6181291e-3f);
    p = fmaf(p, f, 5.5504109e-2f);
    p = fmaf(p, f, 2.4022651e-1f);
    p = fmaf(p, f, 6.9314718e-1f);
    p = fmaf(p, f, 1.0f);
    return p * __int_as_float(((int)n + 127) << 23);
}

// ---------------------------------------------------------------------------
// Flash attention, fp32, online softmax; epilogue emits bf16 hi/lo split.
// ---------------------------------------------------------------------------
#define PST 68
#define FLASH_SMEM ((3 * 64 * 64 + 64 * PST + 3 * 64) * 4)

__global__ __launch_bounds__(256)
void flash_kernel()
{
    extern __shared__ float sm[];
    float* Qs = sm;
    float* Ks = sm + 4096;
    float* Vs = sm + 8192;
    float* Ps = sm + 12288;
    float* m_s = sm + 12288 + 64 * PST;
    float* l_s = m_s + 64;
    float* sc_s = l_s + 64;

    const int tid = threadIdx.x;
    const int tx = tid & 15;
    const int ty = tid >> 4;
    const int bh = blockIdx.y;
    const int b = bh / HH;
    const int h = bh - b * HH;
    const int qbase = blockIdx.x * 64;
    const size_t head_off = ((size_t)b * HH + h) * NT * DD;

    {
        int r = tid >> 2;
        int dc = (tid & 3) << 4;
        const float* src = g_q + head_off + (size_t)(qbase + r) * DD;
        bool valid = (qbase + r) < NT;
#pragma unroll
        for (int u = 0; u < 4; ++u) {
            float4 v = valid ? *(const float4*)(src + dc + u * 4)
                             : make_float4(0.f, 0.f, 0.f, 0.f);
            int d = dc + u * 4;
            Qs[(d + 0) * 64 + r] = v.x; Qs[(d + 1) * 64 + r] = v.y;
            Qs[(d + 2) * 64 + r] = v.z; Qs[(d + 3) * 64 + r] = v.w;
        }
    }
    if (tid < 64) { m_s[tid] = -1e30f; l_s[tid] = 0.0f; }

    float oa[4][4];
#pragma unroll
    for (int i = 0; i < 4; ++i)
#pragma unroll
        for (int c = 0; c < 4; ++c) oa[i][c] = 0.0f;

    for (int t = 0; t < 10; ++t) {
        const int kvbase = t * 64;
        const int vrows = (NT - kvbase < 64) ? (NT - kvbase) : 64;
        __syncthreads();
        {
            int r = tid >> 2;
            int dc = (tid & 3) << 4;
            const float* ksrc = g_k + head_off + (size_t)(kvbase + r) * DD;
            const float* vsrc = g_v + head_off + (size_t)(kvbase + r) * DD;
            bool valid = r < vrows;
#pragma unroll
            for (int u = 0; u < 4; ++u) {
                int d = dc + u * 4;
                float4 kv = valid ? *(const float4*)(ksrc + d)
                                  : make_float4(0.f, 0.f, 0.f, 0.f);
                Ks[(d + 0) * 64 + r] = kv.x; Ks[(d + 1) * 64 + r] = kv.y;
                Ks[(d + 2) * 64 + r] = kv.z; Ks[(d + 3) * 64 + r] = kv.w;
                float4 vv = valid ? *(const float4*)(vsrc + d)
                                  : make_float4(0.f, 0.f, 0.f, 0.f);
                *(float4*)&Vs[r * 64 + d] = vv;
            }
        }
        __syncthreads();

        float s[4][4];
#pragma unroll
        for (int i = 0; i < 4; ++i)
#pragma unroll
            for (int j = 0; j < 4; ++j) s[i][j] = 0.0f;
#pragma unroll 8
        for (int d = 0; d < 64; ++d) {
            float4 qv = *(const float4*)&Qs[d * 64 + ty * 4];
            float4 kv = *(const float4*)&Ks[d * 64 + tx * 4];
            float rq[4] = {qv.x, qv.y, qv.z, qv.w};
            float rk[4] = {kv.x, kv.y, kv.z, kv.w};
#pragma unroll
            for (int i = 0; i < 4; ++i)
#pragma unroll
                for (int j = 0; j < 4; ++j)
                    s[i][j] = fmaf(rq[i], rk[j], s[i][j]);
        }
#pragma unroll
        for (int j = 0; j < 4; ++j) {
            if (kvbase + tx * 4 + j >= NT) {
#pragma unroll
                for (int i = 0; i < 4; ++i) s[i][j] = -1e30f;
            }
        }
        float rmax[4];
#pragma unroll
        for (int i = 0; i < 4; ++i)
            rmax[i] = fmaxf(fmaxf(s[i][0], s[i][1]), fmaxf(s[i][2], s[i][3]));
#pragma unroll
        for (int off = 8; off > 0; off >>= 1)
#pragma unroll
            for (int i = 0; i < 4; ++i)
                rmax[i] = fmaxf(rmax[i], __shfl_xor_sync(0xffffffffu, rmax[i], off));

        float mold[4], mnew[4], rsum[4];
#pragma unroll
        for (int i = 0; i < 4; ++i) {
            mold[i] = m_s[ty * 4 + i];
            mnew[i] = fmaxf(mold[i], rmax[i]);
        }
        float p[4][4];
#pragma unroll
        for (int i = 0; i < 4; ++i) {
            rsum[i] = 0.0f;
#pragma unroll
            for (int j = 0; j < 4; ++j) {
                p[i][j] = fexp(s[i][j] - mnew[i]);
                rsum[i] += p[i][j];
            }
        }
#pragma unroll
        for (int off = 8; off > 0; off >>= 1)
#pragma unroll
            for (int i = 0; i < 4; ++i)
                rsum[i] += __shfl_xor_sync(0xffffffffu, rsum[i], off);

#pragma unroll
        for (int i = 0; i < 4; ++i)
            *(float4*)&Ps[(ty * 4 + i) * PST + tx * 4] =
                make_float4(p[i][0], p[i][1], p[i][2], p[i][3]);

        if (tx == 0) {
#pragma unroll
            for (int i = 0; i < 4; ++i) {
                int r = ty * 4 + i;
                float scl = fexp(mold[i] - mnew[i]);
                m_s[r] = mnew[i];
                sc_s[r] = scl;
                l_s[r] = l_s[r] * scl + rsum[i];
            }
        }
        __syncthreads();

#pragma unroll
        for (int i = 0; i < 4; ++i) {
            float scl = sc_s[ty * 4 + i];
#pragma unroll
            for (int c = 0; c < 4; ++c) oa[i][c] *= scl;
        }
#pragma unroll 4
        for (int j = 0; j < 64; ++j) {
            float4 vv = *(const float4*)&Vs[j * 64 + tx * 4];
#pragma unroll
            for (int i = 0; i < 4; ++i) {
                float pv = Ps[(ty * 4 + i) * PST + j];
                oa[i][0] = fmaf(pv, vv.x, oa[i][0]);
                oa[i][1] = fmaf(pv, vv.y, oa[i][1]);
                oa[i][2] = fmaf(pv, vv.z, oa[i][2]);
                oa[i][3] = fmaf(pv, vv.w, oa[i][3]);
            }
        }
    }

    // normalize + bf16 hi/lo split write to [B,N,H*D]
#pragma unroll
    for (int i = 0; i < 4; ++i) {
        int qr = qbase + ty * 4 + i;
        if (qr < NT) {
            float inv = 1.0f / l_s[ty * 4 + i];
            size_t off = ((size_t)b * NT + qr) * CC + h * DD + tx * 4;
            float vv[4] = {oa[i][0] * inv, oa[i][1] * inv,
                           oa[i][2] * inv, oa[i][3] * inv};
            __nv_bfloat16 hh[4], ll[4];
#pragma unroll
            for (int u = 0; u < 4; ++u) {
                hh[u] = __float2bfloat16(vv[u]);
                ll[u] = __float2bfloat16(vv[u] - __bfloat162float(hh[u]));
            }
            __nv_bfloat162 p0, p1;
            p0.x = hh[0]; p0.y = hh[1]; p1.x = hh[2]; p1.y = hh[3];
            ((__nv_bfloat162*)(g_ohi + off))[0] = p0;
            ((__nv_bfloat162*)(g_ohi + off))[1] = p1;
            p0.x = ll[0]; p0.y = ll[1]; p1.x = ll[2]; p1.y = ll[3];
            ((__nv_bfloat162*)(g_olo + off))[0] = p0;
            ((__nv_bfloat162*)(g_olo + off))[1] = p1;
        }
    }
}

// ---------------------------------------------------------------------------

extern "C" void kernel_launch(void* const* d_in, const int* in_sizes, int n_in,
                              void* d_out, int out_size)
{
    const float* x      = (const float*)d_in[0];
    const float* rope   = (const float*)d_in[1];
    const float* qkv_w  = (const float*)d_in[2];
    const float* q_bias = (const float*)d_in[3];
    const float* v_bias = (const float*)d_in[4];
    const float* proj_w = (const float*)d_in[5];
    const float* proj_b = (const float*)d_in[6];
    float* out = (float*)d_out;
    (void)in_sizes; (void)n_in; (void)out_size;

    // 0) split fp32 inputs/weights into bf16 hi/lo
    const int total4 = (MM * CC + QKV_N * CC + CC * CC) / 4;
    split_kernel<<<(total4 + 255) / 256, 256>>>(x, qkv_w, proj_w);

    const int mtiles = (MM + 127) / 128;   // 145

    // 1) QKV GEMM (mma.sync) + bias + RoPE + q-scale -> g_q/g_k/g_v
    cudaFuncSetAttribute(mma_gemm<0>,
                         cudaFuncAttributeMaxDynamicSharedMemorySize, GEMM_DSMEM);
    mma_gemm<0><<<dim3(QKV_N / 128, mtiles), 256, GEMM_DSMEM>>>(
        q_bias, v_bias, rope, nullptr);

    // 2) flash attention -> g_ohi/g_olo
    cudaFuncSetAttribute(flash_kernel,
                         cudaFuncAttributeMaxDynamicSharedMemorySize, FLASH_SMEM);
    flash_kernel<<<dim3((NT + 63) / 64, BB * HH), 256, FLASH_SMEM>>>();

    // 3) output projection (mma.sync) -> out
    cudaFuncSetAttribute(mma_gemm<1>,
                         cudaFuncAttributeMaxDynamicSharedMemorySize, GEMM_DSMEM);
    mma_gemm<1><<<dim3(CC / 128, mtiles), 256, GEMM_DSMEM>>>(
        proj_b, nullptr, nullptr, out);
}

// round 7
// speedup vs baseline: 2.3766x; 1.5535x over previous
#include <cuda_runtime.h>
#include <cuda_bf16.h>
#include <cstdint>
#include <math.h>

// Problem constants
#define BB 32
#define NT 577
#define HH 12
#define DD 64
#define CC 768
#define MM (BB * NT)        // 18464
#define QKV_N (3 * CC)      // 2304

// ---------------------------------------------------------------------------
// Scratch (static device arrays: allocation-free per harness rules)
// ---------------------------------------------------------------------------
__device__ __nv_bfloat16 g_qh[(size_t)BB * HH * NT * DD];  // [B,H,N,D], scaled
__device__ __nv_bfloat16 g_ql[(size_t)BB * HH * NT * DD];
__device__ __nv_bfloat16 g_kh[(size_t)BB * HH * NT * DD];
__device__ __nv_bfloat16 g_kl[(size_t)BB * HH * NT * DD];
__device__ __nv_bfloat16 g_vh[(size_t)BB * HH * NT * DD];
__device__ __nv_bfloat16 g_vl[(size_t)BB * HH * NT * DD];

__device__ __nv_bfloat16 g_xhi[(size_t)MM * CC];
__device__ __nv_bfloat16 g_xlo[(size_t)MM * CC];
__device__ __nv_bfloat16 g_ohi[(size_t)MM * CC];   // attention out, [B,N,H*D]
__device__ __nv_bfloat16 g_olo[(size_t)MM * CC];
__device__ __nv_bfloat16 g_wqh[(size_t)QKV_N * CC];
__device__ __nv_bfloat16 g_wql[(size_t)QKV_N * CC];
__device__ __nv_bfloat16 g_wph[(size_t)CC * CC];
__device__ __nv_bfloat16 g_wpl[(size_t)CC * CC];

// ---------------------------------------------------------------------------
// Base-sm_100-safe PTX helpers (NO 'a'-gated instructions)
// ---------------------------------------------------------------------------
__device__ __forceinline__ uint32_t smem_u32(const void* p) {
    uint32_t a;
    asm("{ .reg .u64 t; cvta.to.shared.u64 t, %1; cvt.u32.u64 %0, t; }"
        : "=r"(a) : "l"(p));
    return a;
}

#define CP_ASYNC16(dst, src, sz) \
    asm volatile("cp.async.cg.shared.global [%0], [%1], 16, %2;" \
                 :: "r"(dst), "l"(src), "r"(sz))
#define CP_COMMIT() asm volatile("cp.async.commit_group;" ::: "memory")
#define CP_WAIT1()  asm volatile("cp.async.wait_group 1;" ::: "memory")
#define CP_WAIT0()  asm volatile("cp.async.wait_group 0;" ::: "memory")

__device__ __forceinline__ void ldsm_x4(uint32_t (&r)[4], uint32_t addr) {
    asm volatile("ldmatrix.sync.aligned.m8n8.x4.shared.b16 {%0,%1,%2,%3}, [%4];"
                 : "=r"(r[0]), "=r"(r[1]), "=r"(r[2]), "=r"(r[3]) : "r"(addr));
}

__device__ __forceinline__ void ldsm_x4_t(uint32_t (&r)[4], uint32_t addr) {
    asm volatile("ldmatrix.sync.aligned.m8n8.x4.trans.shared.b16 {%0,%1,%2,%3}, [%4];"
                 : "=r"(r[0]), "=r"(r[1]), "=r"(r[2]), "=r"(r[3]) : "r"(addr));
}

__device__ __forceinline__ void mma_bf16(float (&d)[4], const uint32_t (&a)[4],
                                         uint32_t b0, uint32_t b1) {
    asm volatile(
        "mma.sync.aligned.m16n8k16.row.col.f32.bf16.bf16.f32 "
        "{%0,%1,%2,%3}, {%4,%5,%6,%7}, {%8,%9}, {%0,%1,%2,%3};"
        : "+f"(d[0]), "+f"(d[1]), "+f"(d[2]), "+f"(d[3])
        : "r"(a[0]), "r"(a[1]), "r"(a[2]), "r"(a[3]), "r"(b0), "r"(b1));
}

__device__ __forceinline__ void split2(float a, float b,
                                       uint32_t& hi, uint32_t& lo) {
    __nv_bfloat162 h, l;
    h.x = __float2bfloat16(a); h.y = __float2bfloat16(b);
    l.x = __float2bfloat16(a - __bfloat162float(h.x));
    l.y = __float2bfloat16(b - __bfloat162float(h.y));
    hi = *(uint32_t*)&h; lo = *(uint32_t*)&l;
}

// ---------------------------------------------------------------------------
// fp32 -> bf16 hi/lo split of inputs/weights
// ---------------------------------------------------------------------------
__global__ __launch_bounds__(256)
void split_kernel(const float* __restrict__ x, const float* __restrict__ wq,
                  const float* __restrict__ wp)
{
    const int n0 = MM * CC / 4, n1 = QKV_N * CC / 4, n2 = CC * CC / 4;
    int i = blockIdx.x * blockDim.x + threadIdx.x;
    if (i >= n0 + n1 + n2) return;
    const float* src; __nv_bfloat16 *hp, *lp; int j;
    if (i < n0)           { src = x;  hp = g_xhi; lp = g_xlo; j = i; }
    else if (i < n0 + n1) { src = wq; hp = g_wqh; lp = g_wql; j = i - n0; }
    else                  { src = wp; hp = g_wph; lp = g_wpl; j = i - n0 - n1; }
    float4 v = ((const float4*)src)[j];
    uint32_t h0, l0, h1, l1;
    split2(v.x, v.y, h0, l0);
    split2(v.z, v.w, h1, l1);
    ((uint32_t*)(hp + 4 * (size_t)j))[0] = h0;
    ((uint32_t*)(hp + 4 * (size_t)j))[1] = h1;
    ((uint32_t*)(lp + 4 * (size_t)j))[0] = l0;
    ((uint32_t*)(lp + 4 * (size_t)j))[1] = l1;
}

// ---------------------------------------------------------------------------
// mma.sync GEMM (identical mainloop to the validated R5 kernel).
// MODE 0 epilogue now writes q/k/v as bf16 hi/lo in [B,H,N,D].
// ---------------------------------------------------------------------------
#define LDK 40
#define ABYTES (128 * LDK * 2)
#define STAGE_BYTES (4 * ABYTES)
#define GEMM_DSMEM (2 * STAGE_BYTES)
#define NKIT (CC / 32)

template <int MODE>
__global__ __launch_bounds__(256)
void mma_gemm(const float* __restrict__ b0v, const float* __restrict__ b1v,
              const float* __restrict__ rope, float* __restrict__ Cout)
{
    extern __shared__ char dyn[];
    const uint32_t smem_base = smem_u32(dyn);

    const int tid = threadIdx.x;
    const int lane = tid & 31;
    const int wid = tid >> 5;
    const int wm = wid & 1;
    const int wn = wid >> 1;
    const int rowBase = blockIdx.y * 128;
    const int colBase = blockIdx.x * 128;

    const __nv_bfloat16* Ah = (MODE == 0) ? g_xhi : g_ohi;
    const __nv_bfloat16* Al = (MODE == 0) ? g_xlo : g_olo;
    const __nv_bfloat16* Bh = (MODE == 0) ? g_wqh : g_wph;
    const __nv_bfloat16* Bl = (MODE == 0) ? g_wql : g_wpl;

    auto load_stage = [&](int stage, int k0) {
        const uint32_t sb = smem_base + stage * STAGE_BYTES;
#pragma unroll
        for (int t = 0; t < 8; ++t) {
            int c = t * 256 + tid;
            int arr = c >> 9;
            int rid = c & 511;
            int row = rid >> 2;
            int kc = rid & 3;
            uint32_t dst = sb + arr * ABYTES + row * (LDK * 2) + kc * 16;
            const __nv_bfloat16* src;
            int sz = 16;
            if (arr < 2) {
                int m = rowBase + row;
                const __nv_bfloat16* p = arr ? Al : Ah;
                if (m < MM) src = p + (size_t)m * CC + k0 + kc * 8;
                else { src = p; sz = 0; }
            } else {
                const __nv_bfloat16* p = (arr == 2) ? Bh : Bl;
                src = p + (size_t)(colBase + row) * CC + k0 + kc * 8;
            }
            CP_ASYNC16(dst, src, sz);
        }
    };

    float acc[4][4][4];
#pragma unroll
    for (int mf = 0; mf < 4; ++mf)
#pragma unroll
        for (int nf = 0; nf < 4; ++nf)
#pragma unroll
            for (int r = 0; r < 4; ++r) acc[mf][nf][r] = 0.0f;

    const uint32_t lrow = lane & 15;
    const uint32_t lhalf = (lane >> 4) * 8;

    load_stage(0, 0);
    CP_COMMIT();

    for (int c = 0; c < NKIT; ++c) {
        if (c + 1 < NKIT) {
            load_stage((c + 1) & 1, (c + 1) * 32);
            CP_COMMIT();
            CP_WAIT1();
        } else {
            CP_WAIT0();
        }
        __syncthreads();

        const uint32_t sb = smem_base + (c & 1) * STAGE_BYTES;
#pragma unroll
        for (int kk = 0; kk < 32; kk += 16) {
            uint32_t a_h[4][4], a_l[4][4];
#pragma unroll
            for (int mf = 0; mf < 4; ++mf) {
                uint32_t off = ((wm * 64 + mf * 16 + lrow) * LDK + kk + lhalf) * 2;
                ldsm_x4(a_h[mf], sb + off);
                ldsm_x4(a_l[mf], sb + ABYTES + off);
            }
            uint32_t bh[4][2], bl[4][2];
#pragma unroll
            for (int g = 0; g < 2; ++g) {
                uint32_t off = ((wn * 32 + g * 16 + lrow) * LDK + kk + lhalf) * 2;
                uint32_t r[4];
                ldsm_x4(r, sb + 2 * ABYTES + off);
                bh[g * 2][0] = r[0]; bh[g * 2][1] = r[2];
                bh[g * 2 + 1][0] = r[1]; bh[g * 2 + 1][1] = r[3];
                ldsm_x4(r, sb + 3 * ABYTES + off);
                bl[g * 2][0] = r[0]; bl[g * 2][1] = r[2];
                bl[g * 2 + 1][0] = r[1]; bl[g * 2 + 1][1] = r[3];
            }
#pragma unroll
            for (int mf = 0; mf < 4; ++mf)
#pragma unroll
                for (int nf = 0; nf < 4; ++nf) {
                    mma_bf16(acc[mf][nf], a_h[mf], bh[nf][0], bh[nf][1]);
                    mma_bf16(acc[mf][nf], a_h[mf], bl[nf][0], bl[nf][1]);
                    mma_bf16(acc[mf][nf], a_l[mf], bh[nf][0], bh[nf][1]);
                }
        }
        __syncthreads();
    }

    const int r0 = lane >> 2;
    const int c0 = (lane & 3) * 2;
    const int cb = colBase + wn * 32 + c0;

    if (MODE == 0) {
        const int which = colBase / CC;
        __nv_bfloat16* dsth = (which == 0) ? g_qh : (which == 1) ? g_kh : g_vh;
        __nv_bfloat16* dstl = (which == 0) ? g_ql : (which == 1) ? g_kl : g_vl;
#pragma unroll
        for (int mf = 0; mf < 4; ++mf) {
#pragma unroll
            for (int half = 0; half < 2; ++half) {
                int m = rowBase + wm * 64 + mf * 16 + r0 + half * 8;
                if (m >= MM) continue;
                int bbr = m / NT;
                int tt = m - bbr * NT;
                const float* rp = rope + (size_t)(tt - 1) * (2 * DD);
#pragma unroll
                for (int nf = 0; nf < 4; ++nf) {
                    int rel = cb + nf * 8 - which * CC;
                    int h = rel >> 6;
                    int d0i = rel & 63;
                    float v0 = acc[mf][nf][half * 2 + 0];
                    float v1 = acc[mf][nf][half * 2 + 1];
                    if (which == 0) { v0 += b0v[rel]; v1 += b0v[rel + 1]; }
                    else if (which == 2) { v0 += b1v[rel]; v1 += b1v[rel + 1]; }
                    if (which < 2 && tt > 0) {
                        float sn0 = rp[d0i], sn1 = rp[d0i + 1];
                        float cs0 = rp[DD + d0i], cs1 = rp[DD + d0i + 1];
                        float xe = v0, xo = v1;
                        v0 = xe * cs0 - xo * sn0;
                        v1 = xo * cs1 + xe * sn1;
                    }
                    if (which == 0) { v0 *= 0.125f; v1 *= 0.125f; }
                    size_t idx = (((size_t)bbr * HH + h) * NT + tt) * DD + d0i;
                    uint32_t hi, lo;
                    split2(v0, v1, hi, lo);
                    *(uint32_t*)(dsth + idx) = hi;
                    *(uint32_t*)(dstl + idx) = lo;
                }
            }
        }
    } else {
#pragma unroll
        for (int mf = 0; mf < 4; ++mf) {
#pragma unroll
            for (int half = 0; half < 2; ++half) {
                int m = rowBase + wm * 64 + mf * 16 + r0 + half * 8;
                if (m >= MM) continue;
#pragma unroll
                for (int nf = 0; nf < 4; ++nf) {
                    int col = cb + nf * 8;
                    float v0 = acc[mf][nf][half * 2 + 0] + b0v[col];
                    float v1 = acc[mf][nf][half * 2 + 1] + b0v[col + 1];
                    *(float2*)(Cout + (size_t)m * CC + col) = make_float2(v0, v1);
                }
            }
        }
    }
}

// ---------------------------------------------------------------------------
// Fast exp on the FMA pipe
// ---------------------------------------------------------------------------
__device__ __forceinline__ float fexp(float x) {
    x = fmaxf(x, -80.0f);
    float y = x * 1.4426950408889634f;
    float n = rintf(y);
    float f = y - n;
    float p = 1.5402356e-4f;
    p = fmaf(p, f, 1.3333558e-3f);
    p = fmaf(p, f, 9.6181291e-3f);
    p = fmaf(p, f, 5.5504109e-2f);
    p = fmaf(p, f, 2.4022651e-1f);
    p = fmaf(p, f, 6.9314718e-1f);
    p = fmaf(p, f, 1.0f);
    return p * __int_as_float(((int)n + 127) << 23);
}

// ---------------------------------------------------------------------------
// Tensor-core flash attention: 64 q-rows/CTA, 128 threads (4 warps x m16),
// bf16-split S and PV MMAs, register softmax, cp.async double-buffered K/V.
// ---------------------------------------------------------------------------
#define LDV 72                          // padded row (144 B): conflict-free
#define FL_ARR 9216                     // 64*72*2 bytes per array
#define FL_KV 18432                     // after Qh, Ql
#define FL_STG 36864                    // Kh,Kl,Vh,Vl per stage
#define FL_SMEM (FL_KV + 2 * FL_STG)    // 92160 B

__global__ __launch_bounds__(128)
void flash_mma()
{
    extern __shared__ char fsm[];
    const uint32_t sb = smem_u32(fsm);
    const int tid = threadIdx.x;
    const int lane = tid & 31;
    const int wid = tid >> 5;
    const int bh = blockIdx.y;
    const int b = bh / HH;
    const int h = bh - b * HH;
    const int qbase = blockIdx.x * 64;
    const size_t head = ((size_t)b * HH + h) * NT * DD;

    // Q hi/lo tile: 1024 x 16B chunks
#pragma unroll
    for (int t = 0; t < 8; ++t) {
        int c = t * 128 + tid;
        int arr = c >> 9, rid = c & 511;
        int row = rid >> 3, kc = rid & 7;
        const __nv_bfloat16* src =
            (arr ? g_ql : g_qh) + head + (size_t)(qbase + row) * DD + kc * 8;
        int sz = (qbase + row < NT) ? 16 : 0;
        CP_ASYNC16(sb + arr * FL_ARR + row * 144 + kc * 16, src, sz);
    }

    auto load_kv = [&](int t, int s) {
        const int kvb = t * 64;
        const uint32_t base = sb + FL_KV + s * FL_STG;
#pragma unroll
        for (int u = 0; u < 16; ++u) {
            int c = u * 128 + tid;
            int arr = c >> 9, rid = c & 511;
            int row = rid >> 3, kc = rid & 7;
            const __nv_bfloat16* sp =
                (arr == 0) ? g_kh : (arr == 1) ? g_kl : (arr == 2) ? g_vh : g_vl;
            const __nv_bfloat16* src = sp + head + (size_t)(kvb + row) * DD + kc * 8;
            int sz = (kvb + row < NT) ? 16 : 0;
            CP_ASYNC16(base + arr * FL_ARR + row * 144 + kc * 16, src, sz);
        }
    };

    load_kv(0, 0);
    CP_COMMIT();

    float oacc[8][4];
#pragma unroll
    for (int nf = 0; nf < 8; ++nf)
#pragma unroll
        for (int r = 0; r < 4; ++r) oacc[nf][r] = 0.0f;
    float m0 = -1e30f, m1 = -1e30f, l0 = 0.0f, l1 = 0.0f;

    const uint32_t lrow = lane & 15;
    const uint32_t lhalf = (lane >> 4) * 8;
    const uint32_t vrow = (lane & 7) + 8 * ((lane >> 3) & 1);
    const uint32_t vcol = 8 * (lane >> 4);

    for (int t = 0; t < 10; ++t) {
        if (t + 1 < 10) { load_kv(t + 1, (t + 1) & 1); CP_COMMIT(); CP_WAIT1(); }
        else            { CP_WAIT0(); }
        __syncthreads();
        const uint32_t kb = sb + FL_KV + (t & 1) * FL_STG;

        // ---- S = Q K^T (bf16 split, fp32 accum) ----
        float sacc[8][4];
#pragma unroll
        for (int nf = 0; nf < 8; ++nf)
#pragma unroll
            for (int r = 0; r < 4; ++r) sacc[nf][r] = 0.0f;
#pragma unroll
        for (int kf = 0; kf < 4; ++kf) {
            uint32_t offa = ((wid * 16 + lrow) * LDV + kf * 16 + lhalf) * 2;
            uint32_t aqh[4], aql[4];
            ldsm_x4(aqh, sb + offa);
            ldsm_x4(aql, sb + FL_ARR + offa);
#pragma unroll
            for (int ng = 0; ng < 4; ++ng) {
                uint32_t offb = ((ng * 16 + lrow) * LDV + kf * 16 + lhalf) * 2;
                uint32_t rk[4], rl[4];
                ldsm_x4(rk, kb + offb);
                ldsm_x4(rl, kb + FL_ARR + offb);
                mma_bf16(sacc[2 * ng],     aqh, rk[0], rk[2]);
                mma_bf16(sacc[2 * ng + 1], aqh, rk[1], rk[3]);
                mma_bf16(sacc[2 * ng],     aqh, rl[0], rl[2]);
                mma_bf16(sacc[2 * ng + 1], aqh, rl[1], rl[3]);
                mma_bf16(sacc[2 * ng],     aql, rk[0], rk[2]);
                mma_bf16(sacc[2 * ng + 1], aql, rk[1], rk[3]);
            }
        }

        // ---- mask invalid kv columns (last tile only) ----
        const int kvb = t * 64;
        if (kvb + 64 > NT) {
#pragma unroll
            for (int nf = 0; nf < 8; ++nf) {
                int col = kvb + nf * 8 + (lane & 3) * 2;
                if (col >= NT)     { sacc[nf][0] = -1e30f; sacc[nf][2] = -1e30f; }
                if (col + 1 >= NT) { sacc[nf][1] = -1e30f; sacc[nf][3] = -1e30f; }
            }
        }

        // ---- online softmax (rows live in lane quads) ----
        float mx0 = -1e30f, mx1 = -1e30f;
#pragma unroll
        for (int nf = 0; nf < 8; ++nf) {
            mx0 = fmaxf(mx0, fmaxf(sacc[nf][0], sacc[nf][1]));
            mx1 = fmaxf(mx1, fmaxf(sacc[nf][2], sacc[nf][3]));
        }
        mx0 = fmaxf(mx0, __shfl_xor_sync(0xffffffffu, mx0, 1));
        mx0 = fmaxf(mx0, __shfl_xor_sync(0xffffffffu, mx0, 2));
        mx1 = fmaxf(mx1, __shfl_xor_sync(0xffffffffu, mx1, 1));
        mx1 = fmaxf(mx1, __shfl_xor_sync(0xffffffffu, mx1, 2));
        float mn0 = fmaxf(m0, mx0), mn1 = fmaxf(m1, mx1);
        float scl0 = fexp(m0 - mn0), scl1 = fexp(m1 - mn1);
        m0 = mn0; m1 = mn1;

        float rs0 = 0.0f, rs1 = 0.0f;
        uint32_t uph[8][2], upl[8][2];
#pragma unroll
        for (int nf = 0; nf < 8; ++nf) {
            float p0 = fexp(sacc[nf][0] - mn0);
            float p1 = fexp(sacc[nf][1] - mn0);
            float p2 = fexp(sacc[nf][2] - mn1);
            float p3 = fexp(sacc[nf][3] - mn1);
            rs0 += p0 + p1; rs1 += p2 + p3;
            split2(p0, p1, uph[nf][0], upl[nf][0]);
            split2(p2, p3, uph[nf][1], upl[nf][1]);
        }
        rs0 += __shfl_xor_sync(0xffffffffu, rs0, 1);
        rs0 += __shfl_xor_sync(0xffffffffu, rs0, 2);
        rs1 += __shfl_xor_sync(0xffffffffu, rs1, 1);
        rs1 += __shfl_xor_sync(0xffffffffu, rs1, 2);
        l0 = l0 * scl0 + rs0;
        l1 = l1 * scl1 + rs1;
#pragma unroll
        for (int nf = 0; nf < 8; ++nf) {
            oacc[nf][0] *= scl0; oacc[nf][1] *= scl0;
            oacc[nf][2] *= scl1; oacc[nf][3] *= scl1;
        }

        // ---- O += P V (bf16 split; V B-frags via ldmatrix.trans) ----
#pragma unroll
        for (int kf = 0; kf < 4; ++kf) {
            uint32_t ah[4] = {uph[2 * kf][0], uph[2 * kf][1],
                              uph[2 * kf + 1][0], uph[2 * kf + 1][1]};
            uint32_t al[4] = {upl[2 * kf][0], upl[2 * kf][1],
                              upl[2 * kf + 1][0], upl[2 * kf + 1][1]};
#pragma unroll
            for (int g = 0; g < 4; ++g) {
                uint32_t offv = ((kf * 16 + vrow) * LDV + g * 16 + vcol) * 2;
                uint32_t vh[4], vl[4];
                ldsm_x4_t(vh, kb + 2 * FL_ARR + offv);
                ldsm_x4_t(vl, kb + 3 * FL_ARR + offv);
                mma_bf16(oacc[2 * g],     ah, vh[0], vh[1]);
                mma_bf16(oacc[2 * g + 1], ah, vh[2], vh[3]);
                mma_bf16(oacc[2 * g],     ah, vl[0], vl[1]);
                mma_bf16(oacc[2 * g + 1], ah, vl[2], vl[3]);
                mma_bf16(oacc[2 * g],     al, vh[0], vh[1]);
                mma_bf16(oacc[2 * g + 1], al, vh[2], vh[3]);
            }
        }
        __syncthreads();
    }

    // ---- normalize + bf16 hi/lo write to [B,N,H*D] ----
    const float inv0 = 1.0f / l0, inv1 = 1.0f / l1;
    const int qr0 = qbase + wid * 16 + (lane >> 2);
    const int d0 = (lane & 3) * 2;
    if (qr0 < NT) {
        size_t o = ((size_t)b * NT + qr0) * CC + h * DD;
#pragma unroll
        for (int nf = 0; nf < 8; ++nf) {
            uint32_t hi, lo;
            split2(oacc[nf][0] * inv0, oacc[nf][1] * inv0, hi, lo);
            *(uint32_t*)(g_ohi + o + nf * 8 + d0) = hi;
            *(uint32_t*)(g_olo + o + nf * 8 + d0) = lo;
        }
    }
    const int qr1 = qr0 + 8;
    if (qr1 < NT) {
        size_t o = ((size_t)b * NT + qr1) * CC + h * DD;
#pragma unroll
        for (int nf = 0; nf < 8; ++nf) {
            uint32_t hi, lo;
            split2(oacc[nf][2] * inv1, oacc[nf][3] * inv1, hi, lo);
            *(uint32_t*)(g_ohi + o + nf * 8 + d0) = hi;
            *(uint32_t*)(g_olo + o + nf * 8 + d0) = lo;
        }
    }
}

// ---------------------------------------------------------------------------

extern "C" void kernel_launch(void* const* d_in, const int* in_sizes, int n_in,
                              void* d_out, int out_size)
{
    const float* x      = (const float*)d_in[0];
    const float* rope   = (const float*)d_in[1];
    const float* qkv_w  = (const float*)d_in[2];
    const float* q_bias = (const float*)d_in[3];
    const float* v_bias = (const float*)d_in[4];
    const float* proj_w = (const float*)d_in[5];
    const float* proj_b = (const float*)d_in[6];
    float* out = (float*)d_out;
    (void)in_sizes; (void)n_in; (void)out_size;

    // 0) split fp32 inputs/weights into bf16 hi/lo
    const int total4 = (MM * CC + QKV_N * CC + CC * CC) / 4;
    split_kernel<<<(total4 + 255) / 256, 256>>>(x, qkv_w, proj_w);

    const int mtiles = (MM + 127) / 128;   // 145

    // 1) QKV GEMM (mma.sync) + bias + RoPE + q-scale -> q/k/v bf16 hi/lo
    cudaFuncSetAttribute(mma_gemm<0>,
                         cudaFuncAttributeMaxDynamicSharedMemorySize, GEMM_DSMEM);
    mma_gemm<0><<<dim3(QKV_N / 128, mtiles), 256, GEMM_DSMEM>>>(
        q_bias, v_bias, rope, nullptr);

    // 2) tensor-core flash attention -> g_ohi/g_olo
    cudaFuncSetAttribute(flash_mma,
                         cudaFuncAttributeMaxDynamicSharedMemorySize, FL_SMEM);
    flash_mma<<<dim3(10, BB * HH), 128, FL_SMEM>>>();

    // 3) output projection (mma.sync) -> out
    cudaFuncSetAttribute(mma_gemm<1>,
                         cudaFuncAttributeMaxDynamicSharedMemorySize, GEMM_DSMEM);
    mma_gemm<1><<<dim3(CC / 128, mtiles), 256, GEMM_DSMEM>>>(
        proj_b, nullptr, nullptr, out);
}